// round 9
// baseline (speedup 1.0000x reference)
#include <cuda_runtime.h>
#include <cuda_fp16.h>
#include <cuda_bf16.h>

// Problem constants: N=100000 nodes, D=512, E=6.4M edges, out_channels=1.
#define MAX_N 100000
#define NEG_SLOPE 0.2f
#define LOG2E 1.4426950408889634f
#define NBLK 148

// Scratch (allocation-free rule: __device__ globals)
__device__ float  g_x[MAX_N];            // projected feature x = F @ W (fp32)
__device__ __half g_xh[MAX_N];           // fp16 copy for the smem gather table
__device__ float4 g_acc4[MAX_N / 2];     // per-dst {num,den} pairs; zero-init, self-cleaned

// Grid-barrier state (persists across graph replays; generation-counted)
__device__ unsigned          g_bar_count = 0;
__device__ volatile unsigned g_bar_gen   = 0;

__device__ __forceinline__ void grid_barrier()
{
    __threadfence();                       // publish this thread's writes
    __syncthreads();                       // whole block arrived + fenced
    if (threadIdx.x == 0) {
        unsigned gen = g_bar_gen;
        if (atomicAdd(&g_bar_count, 1) == NBLK - 1) {
            g_bar_count = 0;
            __threadfence();
            g_bar_gen = gen + 1;           // release
        } else {
            while (g_bar_gen == gen) __nanosleep(64);
        }
    }
    __syncthreads();
}

__device__ __forceinline__ float ex2(float t)
{
    float r;
    asm("ex2.approx.f32 %0, %1;" : "=f"(r) : "f"(t));
    return r;
}

// ---------------------------------------------------------------------------
// Single persistent kernel: matvec | barrier | edge pass | barrier | finalize.
// 148 blocks x 1024 threads, 200 KB dynamic smem (fp16 x gather table).
// ---------------------------------------------------------------------------
__device__ __forceinline__ void process_edge(
    const __half* __restrict__ sx, int s, int d, float as2, float ad2)
{
    float xs = __half2float(sx[s]);
    float xd = __half2float(sx[d]);
    float l  = fmaf(as2, xs, ad2 * xd);        // pre-scaled by log2e
    float t  = fmaxf(l, NEG_SLOPE * l);        // leaky_relu == max(l, 0.2l)
    float w  = ex2(t);
    float num = w * xs;
    float2* acc = reinterpret_cast<float2*>(g_acc4) + d;
    asm volatile("red.global.add.v2.f32 [%0], {%1, %2};"
                 :: "l"(acc), "f"(num), "f"(w) : "memory");
}

__global__ void __launch_bounds__(1024, 1) fused_kernel(
    const float* __restrict__ F, const float* __restrict__ W,
    const int* __restrict__ src, const int* __restrict__ dst,
    int n, int E,
    const float* __restrict__ att_src, const float* __restrict__ att_dst,
    const float* __restrict__ bias,
    float* __restrict__ out)
{
    extern __shared__ __half sx[];
    __shared__ float4 sW[128];

    const int tid  = threadIdx.x;
    const int lane = tid & 31;
    const int warp = tid >> 5;

    // ---------------- Phase 1: x = F @ W (warp per row, grid-strided) -------
    if (tid < 128) sW[tid] = reinterpret_cast<const float4*>(W)[tid];
    __syncthreads();

    {
        int wglobal = blockIdx.x * 32 + warp;          // 4736 warps chip-wide
        for (int row = wglobal; row < n; row += NBLK * 32) {
            const float4* Frow =
                reinterpret_cast<const float4*>(F + (size_t)row * 512);
            float sum = 0.f;
#pragma unroll
            for (int i = 0; i < 4; i++) {
                float4 a = __ldcs(Frow + lane + 32 * i);
                float4 b = sW[lane + 32 * i];
                sum += a.x * b.x + a.y * b.y + a.z * b.z + a.w * b.w;
            }
#pragma unroll
            for (int o = 16; o > 0; o >>= 1)
                sum += __shfl_xor_sync(0xffffffffu, sum, o);
            if (lane == 0) {
                g_x[row]  = sum;
                g_xh[row] = __float2half(sum);
            }
        }
    }

    grid_barrier();                                     // x fully written

    // ---------------- Phase 2: stage x table + edge pass --------------------
    {
        const uint4* xin = reinterpret_cast<const uint4*>(g_xh);
        uint4* xout = reinterpret_cast<uint4*>(sx);
        int nvec = n >> 3;                              // n % 8 == 0
        for (int i = tid; i < nvec; i += 1024) {
            uint4 v;
            asm("ld.global.cg.v4.u32 {%0,%1,%2,%3}, [%4];"
                : "=r"(v.x), "=r"(v.y), "=r"(v.z), "=r"(v.w) : "l"(xin + i));
            xout[i] = v;
        }
    }
    __syncthreads();

    const float as2 = __ldg(att_src) * LOG2E;
    const float ad2 = __ldg(att_dst) * LOG2E;

    {
        int e4 = E / 4;
        int gid    = blockIdx.x * 1024 + tid;
        int stride = NBLK * 1024;
        const int4* src4 = reinterpret_cast<const int4*>(src);
        const int4* dst4 = reinterpret_cast<const int4*>(dst);

        for (int i = gid; i < e4; i += stride) {
            int4 s = __ldcs(src4 + i);
            int4 t = __ldcs(dst4 + i);
            process_edge(sx, s.x, t.x, as2, ad2);
            process_edge(sx, s.y, t.y, as2, ad2);
            process_edge(sx, s.z, t.z, as2, ad2);
            process_edge(sx, s.w, t.w, as2, ad2);
        }
        int etail_base  = e4 * 4;
        int etail_count = E - etail_base;
        if (gid < etail_count)
            process_edge(sx, src[etail_base + gid], dst[etail_base + gid],
                         as2, ad2);
    }

    grid_barrier();                                     // all REDGs visible

    // ---------------- Phase 3: self-loop fold + normalize + clean -----------
    {
        float aa = as2 + ad2;                           // (as+ad)*log2e
        float b  = __ldg(bias);
        int n4 = n >> 2;
        int i = blockIdx.x * 1024 + tid;                // quad index
        if (i < n4) {
            float4 xi, a0, a1;
            asm("ld.global.cg.v4.f32 {%0,%1,%2,%3}, [%4];"
                : "=f"(xi.x), "=f"(xi.y), "=f"(xi.z), "=f"(xi.w)
                : "l"(reinterpret_cast<const float4*>(g_x) + i));
            asm("ld.global.cg.v4.f32 {%0,%1,%2,%3}, [%4];"
                : "=f"(a0.x), "=f"(a0.y), "=f"(a0.z), "=f"(a0.w)
                : "l"(g_acc4 + 2 * i));
            asm("ld.global.cg.v4.f32 {%0,%1,%2,%3}, [%4];"
                : "=f"(a1.x), "=f"(a1.y), "=f"(a1.z), "=f"(a1.w)
                : "l"(g_acc4 + 2 * i + 1));

            float w0 = ex2(fmaxf(aa * xi.x, NEG_SLOPE * (aa * xi.x)));
            float w1 = ex2(fmaxf(aa * xi.y, NEG_SLOPE * (aa * xi.y)));
            float w2 = ex2(fmaxf(aa * xi.z, NEG_SLOPE * (aa * xi.z)));
            float w3 = ex2(fmaxf(aa * xi.w, NEG_SLOPE * (aa * xi.w)));

            float4 o;
            o.x = __fdividef(a0.x + w0 * xi.x, a0.y + w0) + b;
            o.y = __fdividef(a0.z + w1 * xi.y, a0.w + w1) + b;
            o.z = __fdividef(a1.x + w2 * xi.z, a1.y + w2) + b;
            o.w = __fdividef(a1.z + w3 * xi.w, a1.w + w3) + b;
            reinterpret_cast<float4*>(out)[i] = o;

            g_acc4[2 * i]     = make_float4(0.f, 0.f, 0.f, 0.f);  // clean
            g_acc4[2 * i + 1] = make_float4(0.f, 0.f, 0.f, 0.f);
        }
    }
}

// ---------------------------------------------------------------------------
extern "C" void kernel_launch(void* const* d_in, const int* in_sizes, int n_in,
                              void* d_out, int out_size)
{
    const float* F       = (const float*)d_in[0];
    const int*   ei      = (const int*)  d_in[1];
    const float* W       = (const float*)d_in[2];
    const float* att_src = (const float*)d_in[3];
    const float* att_dst = (const float*)d_in[4];
    const float* bias    = (const float*)d_in[5];
    float*       out     = (float*)d_out;

    const int d = in_sizes[2];        // 512
    const int n = in_sizes[0] / d;    // 100000
    const int E = in_sizes[1] / 2;    // 6400000
    const int* src = ei;
    const int* dst = ei + E;

    const int smem_bytes = n * (int)sizeof(__half);     // 200000 B
    static int configured = 0;        // host-side config memo, not a work guard
    if (!configured) {
        cudaFuncSetAttribute(fused_kernel,
                             cudaFuncAttributeMaxDynamicSharedMemorySize,
                             smem_bytes);
        configured = 1;
    }

    fused_kernel<<<NBLK, 1024, smem_bytes>>>(F, W, src, dst, n, E,
                                             att_src, att_dst, bias, out);
}

// round 10
// speedup vs baseline: 1.0847x; 1.0847x over previous
#include <cuda_runtime.h>
#include <cuda_fp16.h>
#include <cuda_bf16.h>

// Problem constants: N=100000 nodes, D=512, E=6.4M edges, out_channels=1.
#define MAX_N 100000
#define NEG_SLOPE 0.2f
#define LOG2E 1.4426950408889634f
#define NBLK 148

// Scratch (allocation-free rule: __device__ globals)
__device__ float  g_x[MAX_N];            // projected feature x = F @ W (fp32)
__device__ __half g_xh[MAX_N];           // fp16 copy for the smem gather table
__device__ float4 g_acc4[MAX_N / 2];     // per-dst {num,den} pairs; zero-init, self-cleaned

// Grid-barrier state (generation-counted => safe across graph replays)
__device__ unsigned          g_bar_count = 0;
__device__ volatile unsigned g_bar_gen   = 0;

__device__ __forceinline__ void grid_barrier()
{
    __threadfence();
    __syncthreads();
    if (threadIdx.x == 0) {
        unsigned gen = g_bar_gen;
        if (atomicAdd(&g_bar_count, 1) == NBLK - 1) {
            g_bar_count = 0;
            __threadfence();
            g_bar_gen = gen + 1;           // release
        } else {
            while (g_bar_gen == gen) __nanosleep(64);
        }
    }
    __syncthreads();
}

__device__ __forceinline__ float ex2(float t)
{
    float r;
    asm("ex2.approx.f32 %0, %1;" : "=f"(r) : "f"(t));
    return r;
}

// ---------------------------------------------------------------------------
// Kernel 1: x = F @ W   (warp per row, fat grid — proven 78% DRAM shape).
// ---------------------------------------------------------------------------
__global__ void __launch_bounds__(256) matvec_kernel(
    const float* __restrict__ F, const float* __restrict__ W, int n)
{
    __shared__ float4 sW[128];
    int tid = threadIdx.x;
    if (tid < 128) sW[tid] = reinterpret_cast<const float4*>(W)[tid];
    __syncthreads();

    int warp = tid >> 5;
    int lane = tid & 31;
    int row  = blockIdx.x * 8 + warp;
    if (row >= n) return;

    const float4* Frow = reinterpret_cast<const float4*>(F + (size_t)row * 512);
    float sum = 0.f;
#pragma unroll
    for (int i = 0; i < 4; i++) {
        float4 a = __ldcs(Frow + lane + 32 * i);
        float4 b = sW[lane + 32 * i];
        sum += a.x * b.x + a.y * b.y + a.z * b.z + a.w * b.w;
    }
#pragma unroll
    for (int o = 16; o > 0; o >>= 1)
        sum += __shfl_xor_sync(0xffffffffu, sum, o);

    if (lane == 0) {
        g_x[row]  = sum;
        g_xh[row] = __float2half(sum);
    }
}

// ---------------------------------------------------------------------------
// Kernel 2: persistent edge pass + grid barrier + inline finalize.
// 148 blocks x 1024 threads, 200 KB smem (occ 1 -> all blocks resident,
// grid barrier is deadlock-free).
// ---------------------------------------------------------------------------
__device__ __forceinline__ void process_edge(
    const __half* __restrict__ sx, int s, int d, float as2, float ad2)
{
    float xs = __half2float(sx[s]);
    float xd = __half2float(sx[d]);
    float l  = fmaf(as2, xs, ad2 * xd);        // pre-scaled by log2e
    float t  = fmaxf(l, NEG_SLOPE * l);        // leaky_relu == max(l, 0.2l)
    float w  = ex2(t);
    float num = w * xs;
    float2* acc = reinterpret_cast<float2*>(g_acc4) + d;
    asm volatile("red.global.add.v2.f32 [%0], {%1, %2};"
                 :: "l"(acc), "f"(num), "f"(w) : "memory");
}

__global__ void __launch_bounds__(1024, 1) edge_finalize_kernel(
    const int* __restrict__ src, const int* __restrict__ dst,
    int n, int E,
    const float* __restrict__ att_src, const float* __restrict__ att_dst,
    const float* __restrict__ bias,
    float* __restrict__ out)
{
    extern __shared__ __half sx[];
    const int tid = threadIdx.x;

    // Stage x table: 100000 halves = 12500 uint4 vector loads from L2.
    {
        const uint4* xin = reinterpret_cast<const uint4*>(g_xh);
        uint4* xout = reinterpret_cast<uint4*>(sx);
        int nvec = n >> 3;                       // n % 8 == 0
        for (int i = tid; i < nvec; i += 1024)
            xout[i] = xin[i];
    }
    __syncthreads();

    const float as2 = __ldg(att_src) * LOG2E;
    const float ad2 = __ldg(att_dst) * LOG2E;

    // ---------------- edge pass (REDG issue floor) --------------------------
    {
        int e4 = E / 4;
        int gid    = blockIdx.x * 1024 + tid;
        int stride = NBLK * 1024;
        const int4* src4 = reinterpret_cast<const int4*>(src);
        const int4* dst4 = reinterpret_cast<const int4*>(dst);

        for (int i = gid; i < e4; i += stride) {
            int4 s = __ldcs(src4 + i);
            int4 t = __ldcs(dst4 + i);
            process_edge(sx, s.x, t.x, as2, ad2);
            process_edge(sx, s.y, t.y, as2, ad2);
            process_edge(sx, s.z, t.z, as2, ad2);
            process_edge(sx, s.w, t.w, as2, ad2);
        }
        int etail_base  = e4 * 4;
        int etail_count = E - etail_base;
        if (gid < etail_count)
            process_edge(sx, src[etail_base + gid], dst[etail_base + gid],
                         as2, ad2);
    }

    grid_barrier();                              // all REDGs globally visible

    // ---------------- finalize: self-loop fold + normalize + clean ----------
    {
        float aa = as2 + ad2;                    // (as+ad)*log2e
        float b  = __ldg(bias);
        int n4 = n >> 2;                         // 25000 quads
        int i = blockIdx.x * 1024 + tid;
        if (i < n4) {
            float4 xi, a0, a1;
            asm("ld.global.cg.v4.f32 {%0,%1,%2,%3}, [%4];"
                : "=f"(xi.x), "=f"(xi.y), "=f"(xi.z), "=f"(xi.w)
                : "l"(reinterpret_cast<const float4*>(g_x) + i));
            asm("ld.global.cg.v4.f32 {%0,%1,%2,%3}, [%4];"
                : "=f"(a0.x), "=f"(a0.y), "=f"(a0.z), "=f"(a0.w)
                : "l"(g_acc4 + 2 * i));
            asm("ld.global.cg.v4.f32 {%0,%1,%2,%3}, [%4];"
                : "=f"(a1.x), "=f"(a1.y), "=f"(a1.z), "=f"(a1.w)
                : "l"(g_acc4 + 2 * i + 1));

            float w0 = ex2(fmaxf(aa * xi.x, NEG_SLOPE * (aa * xi.x)));
            float w1 = ex2(fmaxf(aa * xi.y, NEG_SLOPE * (aa * xi.y)));
            float w2 = ex2(fmaxf(aa * xi.z, NEG_SLOPE * (aa * xi.z)));
            float w3 = ex2(fmaxf(aa * xi.w, NEG_SLOPE * (aa * xi.w)));

            float4 o;
            o.x = __fdividef(a0.x + w0 * xi.x, a0.y + w0) + b;
            o.y = __fdividef(a0.z + w1 * xi.y, a0.w + w1) + b;
            o.z = __fdividef(a1.x + w2 * xi.z, a1.y + w2) + b;
            o.w = __fdividef(a1.z + w3 * xi.w, a1.w + w3) + b;
            reinterpret_cast<float4*>(out)[i] = o;

            g_acc4[2 * i]     = make_float4(0.f, 0.f, 0.f, 0.f);  // clean
            g_acc4[2 * i + 1] = make_float4(0.f, 0.f, 0.f, 0.f);
        }
    }
}

// ---------------------------------------------------------------------------
extern "C" void kernel_launch(void* const* d_in, const int* in_sizes, int n_in,
                              void* d_out, int out_size)
{
    const float* F       = (const float*)d_in[0];
    const int*   ei      = (const int*)  d_in[1];
    const float* W       = (const float*)d_in[2];
    const float* att_src = (const float*)d_in[3];
    const float* att_dst = (const float*)d_in[4];
    const float* bias    = (const float*)d_in[5];
    float*       out     = (float*)d_out;

    const int d = in_sizes[2];        // 512
    const int n = in_sizes[0] / d;    // 100000
    const int E = in_sizes[1] / 2;    // 6400000
    const int* src = ei;
    const int* dst = ei + E;

    const int smem_bytes = n * (int)sizeof(__half);     // 200000 B
    static int configured = 0;        // host-side config memo, not a work guard
    if (!configured) {
        cudaFuncSetAttribute(edge_finalize_kernel,
                             cudaFuncAttributeMaxDynamicSharedMemorySize,
                             smem_bytes);
        configured = 1;
    }

    // 1. projection (fat grid — keeps DRAM at its 78% plateau)
    matvec_kernel<<<(n + 7) / 8, 256>>>(F, W, n);

    // 2. persistent edge pass + barrier + inline finalize
    edge_finalize_kernel<<<NBLK, 1024, smem_bytes>>>(src, dst, n, E,
                                                     att_src, att_dst, bias, out);
}

// round 11
// speedup vs baseline: 1.1342x; 1.0457x over previous
#include <cuda_runtime.h>
#include <cuda_fp16.h>
#include <cuda_bf16.h>

// Problem constants: N=100000 nodes, D=512, E=6.4M edges, out_channels=1.
#define MAX_N 100000
#define NEG_SLOPE 0.2f
#define LOG2E 1.4426950408889634f
#define NBLK 148

// Scratch (allocation-free rule: __device__ globals)
__device__ float  g_x[MAX_N];            // projected feature x = F @ W (fp32)
__device__ __half g_xh[MAX_N];           // fp16 copy for the smem gather table
__device__ float4 g_acc4[MAX_N / 2];     // per-dst {num,den} pairs; zero-init, self-cleaned

// PDL primitives (PTX, avoids device-runtime linkage)
__device__ __forceinline__ void pdl_launch_dependents()
{
    asm volatile("griddepcontrol.launch_dependents;");
}
__device__ __forceinline__ void pdl_wait()
{
    asm volatile("griddepcontrol.wait;" ::: "memory");
}

// ---------------------------------------------------------------------------
// Kernel 1: x = F @ W   (warp per row; proven 78%-DRAM fat-grid shape).
// ---------------------------------------------------------------------------
__global__ void __launch_bounds__(256) matvec_kernel(
    const float* __restrict__ F, const float* __restrict__ W, int n)
{
    __shared__ float4 sW[128];
    int tid = threadIdx.x;
    if (tid < 128) sW[tid] = reinterpret_cast<const float4*>(W)[tid];
    __syncthreads();

    int warp = tid >> 5;
    int lane = tid & 31;
    int row  = blockIdx.x * 8 + warp;
    if (row >= n) { pdl_launch_dependents(); return; }

    const float4* Frow = reinterpret_cast<const float4*>(F + (size_t)row * 512);
    float sum = 0.f;
#pragma unroll
    for (int i = 0; i < 4; i++) {
        float4 a = __ldcs(Frow + lane + 32 * i);
        float4 b = sW[lane + 32 * i];
        sum += a.x * b.x + a.y * b.y + a.z * b.z + a.w * b.w;
    }
#pragma unroll
    for (int o = 16; o > 0; o >>= 1)
        sum += __shfl_xor_sync(0xffffffffu, sum, o);

    if (lane == 0) {
        g_x[row]  = sum;
        g_xh[row] = __float2half(sum);
    }
    pdl_launch_dependents();                 // x written -> edge grid may launch
}

// ---------------------------------------------------------------------------
// Kernel 2: persistent fused edge pass (REDG issue floor).
// x table staged in SMEM as fp16 (200 KB) -> gathers are LDS.
// Softmax max-subtraction dropped (exact ratio invariance; logits are O(1)).
// ---------------------------------------------------------------------------
__device__ __forceinline__ void process_edge(
    const __half* __restrict__ sx, int s, int d, float as2, float ad2)
{
    float xs = __half2float(sx[s]);
    float xd = __half2float(sx[d]);
    float l  = fmaf(as2, xs, ad2 * xd);        // pre-scaled by log2e
    float t  = fmaxf(l, NEG_SLOPE * l);        // leaky_relu == max(l, 0.2l)
    float w  = exp2f(t);
    float num = w * xs;
    float2* acc = reinterpret_cast<float2*>(g_acc4) + d;
    asm volatile("red.global.add.v2.f32 [%0], {%1, %2};"
                 :: "l"(acc), "f"(num), "f"(w) : "memory");
}

__global__ void __launch_bounds__(1024, 1) edge_kernel(
    const int* __restrict__ src, const int* __restrict__ dst,
    int e4, int etail_base, int etail_count, int n,
    const float* __restrict__ att_src, const float* __restrict__ att_dst)
{
    extern __shared__ __half sx[];
    const int tid = threadIdx.x;

    pdl_wait();                              // matvec's g_xh must be visible

    // Stage x table: 100000 halves = 12500 uint4 (16B) vector loads from L2.
    {
        const uint4* xin = reinterpret_cast<const uint4*>(g_xh);
        uint4* xout = reinterpret_cast<uint4*>(sx);
        int nvec = n >> 3;                       // n % 8 == 0 for N=100000
        for (int i = tid; i < nvec; i += 1024)
            xout[i] = xin[i];
    }
    __syncthreads();

    const float as2 = __ldg(att_src) * LOG2E;
    const float ad2 = __ldg(att_dst) * LOG2E;

    int gid    = blockIdx.x * 1024 + tid;
    int stride = NBLK * 1024;

    const int4* src4 = reinterpret_cast<const int4*>(src);
    const int4* dst4 = reinterpret_cast<const int4*>(dst);

    for (int i = gid; i < e4; i += stride) {
        int4 s = __ldcs(src4 + i);
        int4 t = __ldcs(dst4 + i);
        process_edge(sx, s.x, t.x, as2, ad2);
        process_edge(sx, s.y, t.y, as2, ad2);
        process_edge(sx, s.z, t.z, as2, ad2);
        process_edge(sx, s.w, t.w, as2, ad2);
    }
    // scalar tail (E not divisible by 4)
    if (gid < etail_count)
        process_edge(sx, src[etail_base + gid], dst[etail_base + gid], as2, ad2);

    pdl_launch_dependents();                 // REDGs posted -> finalize may launch
}

// ---------------------------------------------------------------------------
// Kernel 3: fold self-loop, normalize, bias; SELF-CLEAN g_acc for next replay.
// 4 nodes/thread, 128-thread blocks -> 196 blocks (single wave).
// ---------------------------------------------------------------------------
__global__ void __launch_bounds__(128) finalize_kernel(
    float* __restrict__ out, int n4,
    const float* __restrict__ att_src, const float* __restrict__ att_dst,
    const float* __restrict__ bias)
{
    int i = blockIdx.x * blockDim.x + threadIdx.x;   // quad index
    pdl_wait();                              // edge REDGs must be visible
    if (i >= n4) return;
    float aa = (__ldg(att_src) + __ldg(att_dst)) * LOG2E;
    float b  = __ldg(bias);

    float4 xi = reinterpret_cast<const float4*>(g_x)[i];
    float4 a0 = g_acc4[2 * i];
    float4 a1 = g_acc4[2 * i + 1];

    float w0 = exp2f(fmaxf(aa * xi.x, NEG_SLOPE * (aa * xi.x)));
    float w1 = exp2f(fmaxf(aa * xi.y, NEG_SLOPE * (aa * xi.y)));
    float w2 = exp2f(fmaxf(aa * xi.z, NEG_SLOPE * (aa * xi.z)));
    float w3 = exp2f(fmaxf(aa * xi.w, NEG_SLOPE * (aa * xi.w)));

    float4 o;
    o.x = __fdividef(a0.x + w0 * xi.x, a0.y + w0) + b;
    o.y = __fdividef(a0.z + w1 * xi.y, a0.w + w1) + b;
    o.z = __fdividef(a1.x + w2 * xi.z, a1.y + w2) + b;
    o.w = __fdividef(a1.z + w3 * xi.w, a1.w + w3) + b;
    reinterpret_cast<float4*>(out)[i] = o;

    g_acc4[2 * i]     = make_float4(0.f, 0.f, 0.f, 0.f);  // clean for next replay
    g_acc4[2 * i + 1] = make_float4(0.f, 0.f, 0.f, 0.f);
}

// ---------------------------------------------------------------------------
extern "C" void kernel_launch(void* const* d_in, const int* in_sizes, int n_in,
                              void* d_out, int out_size)
{
    const float* F       = (const float*)d_in[0];
    const int*   ei      = (const int*)  d_in[1];
    const float* W       = (const float*)d_in[2];
    const float* att_src = (const float*)d_in[3];
    const float* att_dst = (const float*)d_in[4];
    const float* bias    = (const float*)d_in[5];
    float*       out     = (float*)d_out;

    const int d = in_sizes[2];        // 512
    const int n = in_sizes[0] / d;    // 100000 (divisible by 4)
    const int E = in_sizes[1] / 2;    // 6400000
    const int* srcp = ei;
    const int* dstp = ei + E;

    const int smem_bytes = n * (int)sizeof(__half);     // 200000 B
    static int configured = 0;        // host-side config memo, not a work guard
    if (!configured) {
        cudaFuncSetAttribute(edge_kernel,
                             cudaFuncAttributeMaxDynamicSharedMemorySize,
                             smem_bytes);
        configured = 1;
    }

    // 1. projection (plain launch)
    matvec_kernel<<<(n + 7) / 8, 256>>>(F, W, n);

    // PDL attribute for the dependent launches
    cudaLaunchAttribute pdl_attr;
    pdl_attr.id = cudaLaunchAttributeProgrammaticStreamSerialization;
    pdl_attr.val.programmaticStreamSerializationAllowed = 1;

    // 2. edge pass — PDL-dependent on matvec
    {
        int e4 = E / 4;
        int etail_base  = e4 * 4;
        int etail_count = E - etail_base;

        cudaLaunchConfig_t cfg = {};
        cfg.gridDim          = dim3(NBLK, 1, 1);
        cfg.blockDim         = dim3(1024, 1, 1);
        cfg.dynamicSmemBytes = smem_bytes;
        cfg.stream           = 0;
        cfg.attrs            = &pdl_attr;
        cfg.numAttrs         = 1;
        cudaLaunchKernelEx(&cfg, edge_kernel, srcp, dstp,
                           e4, etail_base, etail_count, n, att_src, att_dst);
    }

    // 3. finalize — PDL-dependent on edge pass
    {
        int n4 = n / 4;
        cudaLaunchConfig_t cfg = {};
        cfg.gridDim          = dim3((n4 + 127) / 128, 1, 1);
        cfg.blockDim         = dim3(128, 1, 1);
        cfg.dynamicSmemBytes = 0;
        cfg.stream           = 0;
        cfg.attrs            = &pdl_attr;
        cfg.numAttrs         = 1;
        cudaLaunchKernelEx(&cfg, finalize_kernel, out, n4,
                           att_src, att_dst, bias);
    }
}

// round 12
// speedup vs baseline: 1.1527x; 1.0163x over previous
#include <cuda_runtime.h>
#include <cuda_fp16.h>
#include <cuda_bf16.h>

// Problem constants: N=100000 nodes, D=512, E=6.4M edges, out_channels=1.
#define MAX_N 100000
#define NEG_SLOPE 0.2f
#define LOG2E 1.4426950408889634f
#define NBLK 148

// Scratch (allocation-free rule: __device__ globals)
__device__ __half g_xh[MAX_N];           // fp16 projected feature (only copy)
__device__ float4 g_acc4[MAX_N / 2];     // per-dst {num,den} pairs; zero-init, self-cleaned

// PDL primitives (PTX)
__device__ __forceinline__ void pdl_launch_dependents()
{
    asm volatile("griddepcontrol.launch_dependents;");
}
__device__ __forceinline__ void pdl_wait()
{
    asm volatile("griddepcontrol.wait;" ::: "memory");
}

// ---------------------------------------------------------------------------
// Kernel 1: x = F @ W   (warp per row; proven 78%-DRAM fat-grid shape).
// Writes only the fp16 table now (finalize reads fp16 too).
// ---------------------------------------------------------------------------
__global__ void __launch_bounds__(256) matvec_kernel(
    const float* __restrict__ F, const float* __restrict__ W, int n)
{
    __shared__ float4 sW[128];
    int tid = threadIdx.x;
    if (tid < 128) sW[tid] = reinterpret_cast<const float4*>(W)[tid];
    __syncthreads();

    int warp = tid >> 5;
    int lane = tid & 31;
    int row  = blockIdx.x * 8 + warp;
    if (row >= n) { pdl_launch_dependents(); return; }

    const float4* Frow = reinterpret_cast<const float4*>(F + (size_t)row * 512);
    float sum = 0.f;
#pragma unroll
    for (int i = 0; i < 4; i++) {
        float4 a = __ldcs(Frow + lane + 32 * i);
        float4 b = sW[lane + 32 * i];
        sum += a.x * b.x + a.y * b.y + a.z * b.z + a.w * b.w;
    }
#pragma unroll
    for (int o = 16; o > 0; o >>= 1)
        sum += __shfl_xor_sync(0xffffffffu, sum, o);

    if (lane == 0)
        g_xh[row] = __float2half(sum);
    pdl_launch_dependents();                 // x written -> edge grid may launch
}

// ---------------------------------------------------------------------------
// Kernel 2: persistent fused edge pass (REDG issue floor).
// x table staged in SMEM as fp16 (200 KB) -> gathers are LDS.
// Softmax max-subtraction dropped (exact ratio invariance; logits are O(1)).
// ---------------------------------------------------------------------------
__device__ __forceinline__ void process_edge(
    const __half* __restrict__ sx, int s, int d, float as2, float ad2)
{
    float xs = __half2float(sx[s]);
    float xd = __half2float(sx[d]);
    float l  = fmaf(as2, xs, ad2 * xd);        // pre-scaled by log2e
    float t  = fmaxf(l, NEG_SLOPE * l);        // leaky_relu == max(l, 0.2l)
    float w  = exp2f(t);
    float num = w * xs;
    float2* acc = reinterpret_cast<float2*>(g_acc4) + d;
    asm volatile("red.global.add.v2.f32 [%0], {%1, %2};"
                 :: "l"(acc), "f"(num), "f"(w) : "memory");
}

__global__ void __launch_bounds__(1024, 1) edge_kernel(
    const int* __restrict__ src, const int* __restrict__ dst,
    int e4, int etail_base, int etail_count, int n,
    const float* __restrict__ att_src, const float* __restrict__ att_dst)
{
    extern __shared__ __half sx[];
    const int tid = threadIdx.x;

    pdl_wait();                              // matvec's g_xh must be visible

    // Stage x table: 100000 halves = 12500 uint4 (16B) vector loads from L2.
    {
        const uint4* xin = reinterpret_cast<const uint4*>(g_xh);
        uint4* xout = reinterpret_cast<uint4*>(sx);
        int nvec = n >> 3;                       // n % 8 == 0 for N=100000
        for (int i = tid; i < nvec; i += 1024)
            xout[i] = xin[i];
    }
    __syncthreads();

    const float as2 = __ldg(att_src) * LOG2E;
    const float ad2 = __ldg(att_dst) * LOG2E;

    int gid    = blockIdx.x * 1024 + tid;
    int stride = NBLK * 1024;

    const int4* src4 = reinterpret_cast<const int4*>(src);
    const int4* dst4 = reinterpret_cast<const int4*>(dst);

#pragma unroll 2
    for (int i = gid; i < e4; i += stride) {
        int4 s = __ldcs(src4 + i);
        int4 t = __ldcs(dst4 + i);
        process_edge(sx, s.x, t.x, as2, ad2);
        process_edge(sx, s.y, t.y, as2, ad2);
        process_edge(sx, s.z, t.z, as2, ad2);
        process_edge(sx, s.w, t.w, as2, ad2);
    }
    // scalar tail (E not divisible by 4)
    if (gid < etail_count)
        process_edge(sx, src[etail_base + gid], dst[etail_base + gid], as2, ad2);

    pdl_launch_dependents();                 // REDGs posted -> finalize may launch
}

// ---------------------------------------------------------------------------
// Kernel 3: fold self-loop, normalize, bias; SELF-CLEAN g_acc for next replay.
// 4 nodes/thread (fp16 x reads), 128-thread blocks -> 196 blocks.
// ---------------------------------------------------------------------------
__global__ void __launch_bounds__(128) finalize_kernel(
    float* __restrict__ out, int n4,
    const float* __restrict__ att_src, const float* __restrict__ att_dst,
    const float* __restrict__ bias)
{
    int i = blockIdx.x * blockDim.x + threadIdx.x;   // quad index
    pdl_wait();                              // edge REDGs must be visible
    if (i >= n4) return;
    float aa = (__ldg(att_src) + __ldg(att_dst)) * LOG2E;
    float b  = __ldg(bias);

    const __half2* xh2 = reinterpret_cast<const __half2*>(g_xh);
    float2 p0 = __half22float2(xh2[2 * i]);
    float2 p1 = __half22float2(xh2[2 * i + 1]);
    float4 a0 = g_acc4[2 * i];
    float4 a1 = g_acc4[2 * i + 1];

    float w0 = exp2f(fmaxf(aa * p0.x, NEG_SLOPE * (aa * p0.x)));
    float w1 = exp2f(fmaxf(aa * p0.y, NEG_SLOPE * (aa * p0.y)));
    float w2 = exp2f(fmaxf(aa * p1.x, NEG_SLOPE * (aa * p1.x)));
    float w3 = exp2f(fmaxf(aa * p1.y, NEG_SLOPE * (aa * p1.y)));

    float4 o;
    o.x = __fdividef(a0.x + w0 * p0.x, a0.y + w0) + b;
    o.y = __fdividef(a0.z + w1 * p0.y, a0.w + w1) + b;
    o.z = __fdividef(a1.x + w2 * p1.x, a1.y + w2) + b;
    o.w = __fdividef(a1.z + w3 * p1.y, a1.w + w3) + b;
    reinterpret_cast<float4*>(out)[i] = o;

    g_acc4[2 * i]     = make_float4(0.f, 0.f, 0.f, 0.f);  // clean for next replay
    g_acc4[2 * i + 1] = make_float4(0.f, 0.f, 0.f, 0.f);
}

// ---------------------------------------------------------------------------
extern "C" void kernel_launch(void* const* d_in, const int* in_sizes, int n_in,
                              void* d_out, int out_size)
{
    const float* F       = (const float*)d_in[0];
    const int*   ei      = (const int*)  d_in[1];
    const float* W       = (const float*)d_in[2];
    const float* att_src = (const float*)d_in[3];
    const float* att_dst = (const float*)d_in[4];
    const float* bias    = (const float*)d_in[5];
    float*       out     = (float*)d_out;

    const int d = in_sizes[2];        // 512
    const int n = in_sizes[0] / d;    // 100000 (divisible by 4)
    const int E = in_sizes[1] / 2;    // 6400000
    const int* srcp = ei;
    const int* dstp = ei + E;

    const int smem_bytes = n * (int)sizeof(__half);     // 200000 B
    static int configured = 0;        // host-side config memo, not a work guard
    if (!configured) {
        cudaFuncSetAttribute(edge_kernel,
                             cudaFuncAttributeMaxDynamicSharedMemorySize,
                             smem_bytes);
        configured = 1;
    }

    // 1. projection (plain launch)
    matvec_kernel<<<(n + 7) / 8, 256>>>(F, W, n);

    // PDL attribute for the dependent launches
    cudaLaunchAttribute pdl_attr;
    pdl_attr.id = cudaLaunchAttributeProgrammaticStreamSerialization;
    pdl_attr.val.programmaticStreamSerializationAllowed = 1;

    // 2. edge pass — PDL-dependent on matvec
    {
        int e4 = E / 4;
        int etail_base  = e4 * 4;
        int etail_count = E - etail_base;

        cudaLaunchConfig_t cfg = {};
        cfg.gridDim          = dim3(NBLK, 1, 1);
        cfg.blockDim         = dim3(1024, 1, 1);
        cfg.dynamicSmemBytes = smem_bytes;
        cfg.stream           = 0;
        cfg.attrs            = &pdl_attr;
        cfg.numAttrs         = 1;
        cudaLaunchKernelEx(&cfg, edge_kernel, srcp, dstp,
                           e4, etail_base, etail_count, n, att_src, att_dst);
    }

    // 3. finalize — PDL-dependent on edge pass
    {
        int n4 = n / 4;
        cudaLaunchConfig_t cfg = {};
        cfg.gridDim          = dim3((n4 + 127) / 128, 1, 1);
        cfg.blockDim         = dim3(128, 1, 1);
        cfg.dynamicSmemBytes = 0;
        cfg.stream           = 0;
        cfg.attrs            = &pdl_attr;
        cfg.numAttrs         = 1;
        cudaLaunchKernelEx(&cfg, finalize_kernel, out, n4,
                           att_src, att_dst, bias);
    }
}